// round 1
// baseline (speedup 1.0000x reference)
#include <cuda_runtime.h>
#include <cuda_bf16.h>
#include <math_constants.h>

// Problem constants
#define BATCH   32
#define SEQ     257
#define EMBED   1024
#define HEADS   16
#define HEAD_D  64
#define M_ROWS  (BATCH * SEQ)        // 8224
#define ATTN_SCALE 0.125f            // 64^-0.5

// Scratch (device globals; no allocation allowed)
__device__ float g_q[M_ROWS * EMBED];
__device__ float g_k[M_ROWS * EMBED];
__device__ float g_v[M_ROWS * EMBED];
__device__ float g_ctx[M_ROWS * EMBED];

// ---------------------------------------------------------------------------
// GEMM: C[m,n] = (sum_k A[m,k] * W[n,k] + bias[n]) * scale
// A: [M,1024] row-major, W: [1024,1024] row-major (n,k), N=K=1024 fixed.
// Tiles BM=BN=64, BK=16; 256 threads; 4x4 microtile per thread.
// ---------------------------------------------------------------------------
#define BM 64
#define BN 64
#define BK 16

__global__ __launch_bounds__(256, 4)
void gemm_nt_kernel(const float* __restrict__ A,
                    const float* __restrict__ W,
                    const float* __restrict__ bias,
                    float* __restrict__ C,
                    int M, float scale)
{
    __shared__ float As[BK][BM];   // transposed: As[k][m]
    __shared__ float Bs[BK][BN];   // transposed: Bs[k][n]

    const int tid = threadIdx.x;
    const int tr = tid / 16;       // 0..15 -> row group
    const int tc = tid % 16;       // 0..15 -> col group

    const int ldRow  = tid >> 2;          // 0..63
    const int ldCol4 = (tid & 3) << 2;    // 0,4,8,12

    const int m0 = blockIdx.x * BM;
    const int n0 = blockIdx.y * BN;

    const int gm = m0 + ldRow;            // global row for A loads
    const int gn = n0 + ldRow;            // global row for W loads (always < 1024)
    const bool mOk = (gm < M);

    float acc[4][4];
#pragma unroll
    for (int i = 0; i < 4; i++)
#pragma unroll
        for (int j = 0; j < 4; j++) acc[i][j] = 0.f;

    for (int k0 = 0; k0 < EMBED; k0 += BK) {
        // load A tile (transposed into As)
        float4 fa = make_float4(0.f, 0.f, 0.f, 0.f);
        if (mOk)
            fa = *reinterpret_cast<const float4*>(&A[(size_t)gm * EMBED + k0 + ldCol4]);
        As[ldCol4 + 0][ldRow] = fa.x;
        As[ldCol4 + 1][ldRow] = fa.y;
        As[ldCol4 + 2][ldRow] = fa.z;
        As[ldCol4 + 3][ldRow] = fa.w;

        // load W tile (transposed into Bs)
        float4 fb = *reinterpret_cast<const float4*>(&W[(size_t)gn * EMBED + k0 + ldCol4]);
        Bs[ldCol4 + 0][ldRow] = fb.x;
        Bs[ldCol4 + 1][ldRow] = fb.y;
        Bs[ldCol4 + 2][ldRow] = fb.z;
        Bs[ldCol4 + 3][ldRow] = fb.w;

        __syncthreads();

#pragma unroll
        for (int kk = 0; kk < BK; kk++) {
            float4 a4 = *reinterpret_cast<const float4*>(&As[kk][tr * 4]);
            float4 b4 = *reinterpret_cast<const float4*>(&Bs[kk][tc * 4]);
            float ar[4] = {a4.x, a4.y, a4.z, a4.w};
            float br[4] = {b4.x, b4.y, b4.z, b4.w};
#pragma unroll
            for (int i = 0; i < 4; i++)
#pragma unroll
                for (int j = 0; j < 4; j++)
                    acc[i][j] = fmaf(ar[i], br[j], acc[i][j]);
        }
        __syncthreads();
    }

    // epilogue: bias + scale, guarded store
#pragma unroll
    for (int j = 0; j < 4; j++) {
        const int n = n0 + tc * 4 + j;
        const float bn = bias[n];
#pragma unroll
        for (int i = 0; i < 4; i++) {
            const int m = m0 + tr * 4 + i;
            if (m < M)
                C[(size_t)m * EMBED + n] = (acc[i][j] + bn) * scale;
        }
    }
}

// ---------------------------------------------------------------------------
// Attention: one block per (batch, head). K/V staged in smem (ld=65, padded,
// conflict-free). 8 warps; each warp owns query rows i = w, w+8, ...
// ---------------------------------------------------------------------------
#define LDKV 65
#define NWARP 8

__global__ __launch_bounds__(256, 1)
void attn_kernel()
{
    extern __shared__ float sm[];
    float* Ks = sm;                       // SEQ * LDKV
    float* Vs = Ks + SEQ * LDKV;          // SEQ * LDKV
    float* Ps = Vs + SEQ * LDKV;          // NWARP * SEQ
    float* Qs = Ps + NWARP * SEQ;         // NWARP * 64

    const int tid  = threadIdx.x;
    const int w    = tid >> 5;
    const int lane = tid & 31;
    const int b = blockIdx.x >> 4;
    const int h = blockIdx.x & 15;

    const size_t base = (size_t)b * SEQ * EMBED + h * HEAD_D;

    // stage K and V tiles
    for (int idx = tid; idx < SEQ * 16; idx += 256) {
        const int j = idx >> 4;
        const int c = (idx & 15) << 2;
        float4 fk = *reinterpret_cast<const float4*>(&g_k[base + (size_t)j * EMBED + c]);
        float4 fv = *reinterpret_cast<const float4*>(&g_v[base + (size_t)j * EMBED + c]);
        float* dk = &Ks[j * LDKV + c];
        float* dv = &Vs[j * LDKV + c];
        dk[0] = fk.x; dk[1] = fk.y; dk[2] = fk.z; dk[3] = fk.w;
        dv[0] = fv.x; dv[1] = fv.y; dv[2] = fv.z; dv[3] = fv.w;
    }
    __syncthreads();

    for (int i = w; i < SEQ; i += NWARP) {
        // load Q row (already scaled by ATTN_SCALE in projection)
        const float* qrow = &g_q[base + (size_t)i * EMBED];
        Qs[w * 64 + lane]      = qrow[lane];
        Qs[w * 64 + lane + 32] = qrow[lane + 32];
        __syncwarp();

        // scores: lane handles j = lane + 32*r (r<8); j=256 computed uniformly
        float s[8];
#pragma unroll
        for (int r = 0; r < 8; r++) s[r] = 0.f;
        float s8 = 0.f;  // j = 256, identical on all lanes (broadcast reads)

#pragma unroll 4
        for (int d = 0; d < HEAD_D; d++) {
            const float qd = Qs[w * 64 + d];
#pragma unroll
            for (int r = 0; r < 8; r++)
                s[r] = fmaf(qd, Ks[(lane + (r << 5)) * LDKV + d], s[r]);
            s8 = fmaf(qd, Ks[256 * LDKV + d], s8);
        }

        // softmax (warp-level)
        float mx = s[0];
#pragma unroll
        for (int r = 1; r < 8; r++) mx = fmaxf(mx, s[r]);
#pragma unroll
        for (int off = 16; off > 0; off >>= 1)
            mx = fmaxf(mx, __shfl_xor_sync(0xffffffffu, mx, off));
        mx = fmaxf(mx, s8);

        float p[8], lsum = 0.f;
#pragma unroll
        for (int r = 0; r < 8; r++) { p[r] = __expf(s[r] - mx); lsum += p[r]; }
#pragma unroll
        for (int off = 16; off > 0; off >>= 1)
            lsum += __shfl_xor_sync(0xffffffffu, lsum, off);
        const float p8 = __expf(s8 - mx);
        const float inv = 1.f / (lsum + p8);

#pragma unroll
        for (int r = 0; r < 8; r++)
            Ps[w * SEQ + lane + (r << 5)] = p[r] * inv;
        if (lane == 0) Ps[w * SEQ + 256] = p8 * inv;
        __syncwarp();

        // ctx[i,d] = sum_j P[j] * V[j,d]; lane owns d=lane and d=lane+32
        float acc0 = 0.f, acc1 = 0.f;
#pragma unroll 4
        for (int j = 0; j < SEQ; j++) {
            const float pj = Ps[w * SEQ + j];
            acc0 = fmaf(pj, Vs[j * LDKV + lane],      acc0);
            acc1 = fmaf(pj, Vs[j * LDKV + lane + 32], acc1);
        }
        float* crow = &g_ctx[base + (size_t)i * EMBED];
        crow[lane]      = acc0;
        crow[lane + 32] = acc1;
        __syncwarp();
    }
}

// ---------------------------------------------------------------------------
extern "C" void kernel_launch(void* const* d_in, const int* in_sizes, int n_in,
                              void* d_out, int out_size)
{
    const float* X  = (const float*)d_in[0];
    const float* Wq = (const float*)d_in[1];
    const float* bq = (const float*)d_in[2];
    const float* Wk = (const float*)d_in[3];
    const float* bk = (const float*)d_in[4];
    const float* Wv = (const float*)d_in[5];
    const float* bv = (const float*)d_in[6];
    const float* Wo = (const float*)d_in[7];
    const float* bo = (const float*)d_in[8];
    float* out = (float*)d_out;

    float *q, *k, *v, *ctx;
    cudaGetSymbolAddress((void**)&q,   g_q);
    cudaGetSymbolAddress((void**)&k,   g_k);
    cudaGetSymbolAddress((void**)&v,   g_v);
    cudaGetSymbolAddress((void**)&ctx, g_ctx);

    const dim3 gGrid((M_ROWS + BM - 1) / BM, EMBED / BN);
    const dim3 gBlk(256);

    // Q/K/V projections (Q fused with attention scale)
    gemm_nt_kernel<<<gGrid, gBlk>>>(X, Wq, bq, q, M_ROWS, ATTN_SCALE);
    gemm_nt_kernel<<<gGrid, gBlk>>>(X, Wk, bk, k, M_ROWS, 1.0f);
    gemm_nt_kernel<<<gGrid, gBlk>>>(X, Wv, bv, v, M_ROWS, 1.0f);

    // attention
    const int smemBytes = (2 * SEQ * LDKV + NWARP * SEQ + NWARP * 64) * (int)sizeof(float);
    cudaFuncSetAttribute(attn_kernel, cudaFuncAttributeMaxDynamicSharedMemorySize, smemBytes);
    attn_kernel<<<BATCH * HEADS, 256, smemBytes>>>();

    // output projection
    gemm_nt_kernel<<<gGrid, gBlk>>>(ctx, Wo, bo, out, M_ROWS, 1.0f);
}